// round 16
// baseline (speedup 1.0000x reference)
#include <cuda_runtime.h>
#include <cuda_bf16.h>

// ---------------------------------------------------------------------------
// ConvTransE scoring, algebraically reduced:
//   score[i] = e_t[i]^T (proj_w @ relu(conv(x_i)+b) + proj_b),  x_i = [h_e ; r_e]
// Linear/zero channels folded into an effective 512x512 matrix; the few
// "uncertain" channels + the p==511 edge go through exact-ReLU correction
// columns of one fused GEMM. Tensor cores via hi/lo bf16 split (3x mma.sync
// m16n8k16). B kept in natural [k][n] bf16 layout (written coalesced by k3);
// k4 loads B fragments with ldmatrix.trans. 4 launches total.
// ---------------------------------------------------------------------------

#define BATCH    2048
#define DIM      512
#define CH       32
#define NMAXPAD  16960          // max padded N (= 265*64), row stride of Bh/Bl

__device__ __align__(16) float g_H[BATCH * DIM];     // gathered h_e rows (fp32, coefs)
__device__ __align__(16) __nv_bfloat16 g_Ah[BATCH * DIM];   // A hi [m][k]
__device__ __align__(16) __nv_bfloat16 g_Al[BATCH * DIM];   // A lo
__device__ __align__(16) __nv_bfloat16 g_Bh[512 * NMAXPAD]; // B hi [k][n] (zero-init tails)
__device__ __align__(16) __nv_bfloat16 g_Bl[512 * NMAXPAD]; // B lo [k][n]
__device__ float        g_r0[BATCH];               // rel[r[i]][0]
__device__ float        g_bmax[BATCH];             // per-row max|h_e|
__device__ float4       g_weff[CH];                // (w0,w1,w2,b) if linear else 0
__device__ int          g_unc[CH];                 // compact list of uncertain channels
__device__ int          g_uidx[CH];                // channel -> unc index or -1
__device__ int          g_N;                       // runtime #columns = 545 + 511*U

#define MMA_BF16(C, A, B0, B1) \
    asm volatile("mma.sync.aligned.m16n8k16.row.col.f32.bf16.bf16.f32 " \
        "{%0,%1,%2,%3},{%4,%5,%6,%7},{%8,%9},{%0,%1,%2,%3};" \
        : "+f"(C[0]), "+f"(C[1]), "+f"(C[2]), "+f"(C[3]) \
        : "r"(A[0]), "r"(A[1]), "r"(A[2]), "r"(A[3]), "r"(B0), "r"(B1))

#define LDSM_X4(d0, d1, d2, d3, addr) \
    asm volatile("ldmatrix.sync.aligned.m8n8.x4.shared.b16 {%0,%1,%2,%3}, [%4];" \
        : "=r"(d0), "=r"(d1), "=r"(d2), "=r"(d3) : "r"(addr))

#define LDSM_X4_T(d0, d1, d2, d3, addr) \
    asm volatile("ldmatrix.sync.aligned.m8n8.x4.trans.shared.b16 {%0,%1,%2,%3}, [%4];" \
        : "=r"(d0), "=r"(d1), "=r"(d2), "=r"(d3) : "r"(addr))

#define CP_ASYNC_16(dst, src) \
    asm volatile("cp.async.cg.shared.global [%0], [%1], 16;" :: "r"(dst), "l"(src))
#define CP_COMMIT() asm volatile("cp.async.commit_group;")
#define CP_WAIT2()  asm volatile("cp.async.wait_group 2;")
#define CP_WAIT1()  asm volatile("cp.async.wait_group 1;")
#define CP_WAIT0()  asm volatile("cp.async.wait_group 0;")

__device__ __forceinline__ void split_bf16(float v, __nv_bfloat16& hi, __nv_bfloat16& lo) {
    hi = __float2bfloat16(v);
    lo = __float2bfloat16(v - __bfloat162float(hi));
}

// ------------- K1: gather + zero scores + per-row max + A split -------------
// 512 blocks x 256 threads, 4 batch rows per block, 4 independent LDG.128
// per thread (2 per source row) for higher MLP.
__global__ __launch_bounds__(256) void k1_gather(
    const int* __restrict__ h, const int* __restrict__ r, const int* __restrict__ t,
    const float* __restrict__ ent, const float* __restrict__ rel,
    float* __restrict__ out)
{
    const int tid  = threadIdx.x;
    const int warp = tid >> 5;
    const int lane = tid & 31;
    const int row  = warp >> 1;          // 0..3 (block-local batch row)
    const int half = warp & 1;
    const int i    = blockIdx.x * 4 + row;
    const int f4   = half * 64 + lane;   // float4 index (0..63 within half-row)

    const float4* hs = (const float4*)(ent + (size_t)h[i] * DIM);
    const float4* ts = (const float4*)(ent + (size_t)t[i] * DIM);
    float4 hv0 = hs[f4], hv1 = hs[f4 + 32];
    float4 tv0 = ts[f4], tv1 = ts[f4 + 32];
    ((float4*)g_H)[i * 128 + f4]      = hv0;
    ((float4*)g_H)[i * 128 + f4 + 32] = hv1;
    {
        float v[8] = {tv0.x, tv0.y, tv0.z, tv0.w, tv1.x, tv1.y, tv1.z, tv1.w};
        size_t b0 = (size_t)i * DIM + f4 * 4;
        #pragma unroll
        for (int j = 0; j < 4; j++) {
            __nv_bfloat16 hi, lo;
            split_bf16(v[j], hi, lo);
            g_Ah[b0 + j] = hi;  g_Al[b0 + j] = lo;
        }
        size_t b1 = b0 + 128;
        #pragma unroll
        for (int j = 0; j < 4; j++) {
            __nv_bfloat16 hi, lo;
            split_bf16(v[4 + j], hi, lo);
            g_Ah[b1 + j] = hi;  g_Al[b1 + j] = lo;
        }
    }
    float m = fmaxf(fmaxf(fabsf(hv0.x), fabsf(hv0.y)), fmaxf(fabsf(hv0.z), fabsf(hv0.w)));
    m = fmaxf(m, fmaxf(fmaxf(fabsf(hv1.x), fabsf(hv1.y)), fmaxf(fabsf(hv1.z), fabsf(hv1.w))));
    #pragma unroll
    for (int off = 16; off > 0; off >>= 1)
        m = fmaxf(m, __shfl_xor_sync(0xffffffffu, m, off));
    __shared__ float wm[8];
    if (lane == 0) wm[warp] = m;
    __syncthreads();
    if (lane == 0 && half == 0) {
        g_bmax[i] = fmaxf(wm[2 * row], wm[2 * row + 1]);
        g_r0[i] = rel[(size_t)r[i] * DIM];
        out[i] = 0.0f;
    }
}

// ------------- K2: reduce bmax + classify + effective weights ---------------
__global__ __launch_bounds__(128) void k2_classify(
    const float* __restrict__ cw, const float* __restrict__ cb)
{
    __shared__ float sm[4];
    int tid = threadIdx.x;
    float m = 0.0f;
    #pragma unroll
    for (int j = tid; j < BATCH; j += 128) m = fmaxf(m, g_bmax[j]);
    #pragma unroll
    for (int off = 16; off > 0; off >>= 1)
        m = fmaxf(m, __shfl_xor_sync(0xffffffffu, m, off));
    if ((tid & 31) == 0) sm[tid >> 5] = m;
    __syncthreads();
    if (tid < 32) {
        float xmax = fmaxf(fmaxf(sm[0], sm[1]), fmaxf(sm[2], sm[3]));
        int c = tid;
        float w0 = cw[c*3], w1 = cw[c*3+1], w2 = cw[c*3+2], b = cb[c];
        float bound = (fabsf(w0) + fabsf(w1) + fabsf(w2)) * xmax;
        int cls = (b >= bound) ? 1 : ((b <= -bound) ? 0 : 2);
        float lin = (cls == 1) ? 1.0f : 0.0f;
        g_weff[c] = make_float4(w0 * lin, w1 * lin, w2 * lin, b * lin);
        unsigned msk = __ballot_sync(0xffffffffu, cls == 2);
        if (cls == 2) {
            int idx = __popc(msk & ((1u << c) - 1u));
            g_unc[idx] = c;
            g_uidx[c] = idx;
        } else {
            g_uidx[c] = -1;
        }
        if (c == 0) g_N = 545 + 511 * __popc(msk);
    }
}

// ------------- K3: cp.async-streamed fold conv+proj_w -> Bh/Bl [k][n] -------
// 512 blocks x 256 threads, one d-row (= one B k-row) per block. proj_w row
// (64KB) streamed through a 3-stage x 16KB cp.async ring. Branchless
// T-accumulators (thread owns n = 2t, 2t+1); neighbor terms resolved at the
// end via an smem exchange. Writes bf16 hi/lo B rows directly (coalesced);
// columns >= Ncols are never written and stay zero (static init).
#define K3_NSTG 3
__global__ __launch_bounds__(256) void k3_build(
    const float* __restrict__ pw, const float* __restrict__ pb)
{
    __shared__ __align__(16) float stg[K3_NSTG][8 * 512];   // 48KB
    __shared__ float sred[8];
    const int tid = threadIdx.x;
    const int d = blockIdx.x;
    const float* prow = pw + (size_t)d * (CH * DIM);
    const size_t drow = (size_t)d * NMAXPAD;
    const unsigned sb0 = (unsigned)__cvta_generic_to_shared(&stg[0][0]);
    const int n0 = tid * 2;

    float T0[2] = {0,0}, T1[2] = {0,0}, T2[2] = {0,0}, T3[2] = {0,0};

    auto issue = [&](int g) {
        unsigned dstb = sb0 + (unsigned)((g % K3_NSTG) * 8 * 512 * 4);
        const float* src = prow + g * 4096;
        #pragma unroll
        for (int j = 0; j < 4; j++)
            CP_ASYNC_16(dstb + (unsigned)(tid + j * 256) * 16, src + (tid + j * 256) * 4);
        CP_COMMIT();
    };
    issue(0); issue(1); issue(2);

    #pragma unroll 1
    for (int g = 0; g < 4; g++) {
        if (g <= 1) { CP_WAIT2(); }
        else if (g == 2) { CP_WAIT1(); }
        else { CP_WAIT0(); }
        __syncthreads();
        const float* buf = &stg[g % K3_NSTG][0];
        #pragma unroll
        for (int cc = 0; cc < 8; cc++) {
            int c = g * 8 + cc;
            float2 s = *(const float2*)&buf[cc * 512 + n0];
            float4 w = g_weff[c];
            T0[0] = fmaf(w.x, s.x, T0[0]); T0[1] = fmaf(w.x, s.y, T0[1]);
            T1[0] = fmaf(w.y, s.x, T1[0]); T1[1] = fmaf(w.y, s.y, T1[1]);
            T2[0] = fmaf(w.z, s.x, T2[0]); T2[1] = fmaf(w.z, s.y, T2[1]);
            T3[0] = fmaf(w.w, s.x, T3[0]); T3[1] = fmaf(w.w, s.y, T3[1]);
            if (tid == 255) {                              // edge col (p==511)
                __nv_bfloat16 hi, lo;
                split_bf16(s.y, hi, lo);
                g_Bh[drow + 513 + c] = hi;
                g_Bl[drow + 513 + c] = lo;
            }
            int ui = g_uidx[c];
            if (ui >= 0) {                                 // uncertain: exact copy
                size_t base = drow + 545 + (size_t)ui * 511;
                __nv_bfloat16 hi, lo;
                split_bf16(s.x, hi, lo);
                g_Bh[base + n0] = hi;  g_Bl[base + n0] = lo;
                if (n0 + 1 < 511) {
                    split_bf16(s.y, hi, lo);
                    g_Bh[base + n0 + 1] = hi;  g_Bl[base + n0 + 1] = lo;
                }
            }
        }
        __syncthreads();                 // reads done before ring reuse
        if (g == 0) issue(3);
    }

    // end merge: acc[n] = T0[n+1] + T1[n] + T2[n-1] via smem exchange
    float* sT = &stg[0][0];              // reuse: 3*512 floats
    sT[n0] = T0[0];        sT[n0 + 1] = T0[1];
    sT[512 + n0] = T1[0];  sT[512 + n0 + 1] = T1[1];
    sT[1024 + n0] = T2[0]; sT[1024 + n0 + 1] = T2[1];
    __syncthreads();
    {
        int na = n0, nb = n0 + 1;
        float acc0 = 0.0f, acc1 = 0.0f;
        if (na <= 509) acc0 += sT[na + 1];
        if (na <= 510) acc0 += sT[512 + na];
        if (na >= 1)   acc0 += sT[1024 + na - 1];
        if (nb <= 509) acc1 += sT[nb + 1];
        if (nb <= 510) acc1 += sT[512 + nb];
        acc1 += sT[1024 + nb - 1];       // nb >= 1 always
        __nv_bfloat16 h0, l0, h1, l1;
        split_bf16(acc0, h0, l0);
        split_bf16(acc1, h1, l1);
        __nv_bfloat162 hp; hp.x = h0; hp.y = h1;
        __nv_bfloat162 lp; lp.x = l0; lp.y = l1;
        *(__nv_bfloat162*)&g_Bh[drow + n0] = hp;
        *(__nv_bfloat162*)&g_Bl[drow + n0] = lp;
    }
    float cp = T3[0] + ((n0 + 1 <= 510) ? T3[1] : 0.0f);
    #pragma unroll
    for (int off = 16; off > 0; off >>= 1)
        cp += __shfl_xor_sync(0xffffffffu, cp, off);
    if ((tid & 31) == 0) sred[tid >> 5] = cp;
    __syncthreads();
    if (tid == 0) {
        float s = 0.0f;
        #pragma unroll
        for (int w = 0; w < 8; w++) s += sred[w];
        __nv_bfloat16 hi, lo;
        split_bf16(s + pb[d], hi, lo);
        g_Bh[drow + 512] = hi;           // const column
        g_Bl[drow + 512] = lo;
    }
}

// -------------------- coef(row, col) for the scoring epilogue ---------------
__device__ __forceinline__ float coef_fn(int row, int n, int Ncols,
                                         const float* __restrict__ cw,
                                         const float* __restrict__ cb)
{
    if (n >= Ncols) return 0.0f;
    if (n < 512)  return g_H[(size_t)row * DIM + n];
    if (n == 512) return 1.0f;
    const float* Hr = &g_H[(size_t)row * DIM];
    if (n < 545) {
        int c = n - 513;
        float v = fmaf(cw[c * 3], Hr[510],
                  fmaf(cw[c * 3 + 1], Hr[511],
                  fmaf(cw[c * 3 + 2], g_r0[row], cb[c])));
        return fmaxf(v, 0.0f);
    }
    int q = n - 545;
    int ui = q / 511;
    int p = q - ui * 511;                // p in [0, 510]
    int c = g_unc[ui];
    float xm1 = (p == 0) ? 0.0f : Hr[p - 1];
    float v = fmaf(cw[c * 3], xm1,
              fmaf(cw[c * 3 + 1], Hr[p],
              fmaf(cw[c * 3 + 2], Hr[p + 1], cb[c])));
    return fmaxf(v, 0.0f);
}

// ---------- K4: persistent tensor-core GEMM + fused scoring (grid-stride) ---
// 64(m) x 64(n) tiles, k-tile 16, 4-stage cp.async ring (43KB static smem).
// A fragments via ldmatrix (rows padded to 24 bf16); B fragments via
// ldmatrix.trans from natural [k][n] layout (rows padded to 72 bf16 = 144B:
// 8 consecutive k-rows hit 8 distinct 16B quadrants -> conflict-free).
// Stage layout (bf16 elements): AH 0 (64x24), AL 1536, BH 3072 (16x72), BL 4224.
#define K4_STAGE 5376

__global__ __launch_bounds__(128) void k4_gemm(
    const float* __restrict__ cw, const float* __restrict__ cb,
    float* __restrict__ out)
{
    const int Ncols = g_N;
    const int ntn = (Ncols + 63) >> 6;
    const int total = ntn * 32;          // 32 m-tiles of 64

    __shared__ __align__(16) __nv_bfloat16 smem[4 * K4_STAGE];   // 43,008 B
    const unsigned sbase = (unsigned)__cvta_generic_to_shared(smem);

    const int tid  = threadIdx.x;
    const int lane = tid & 31;
    const int wn   = tid >> 5;           // 0..3 (n 16-offset)
    const int g = lane >> 2;             // 0..7
    const int q = lane & 3;              // 0..3

    // A cp.async mapping (128 threads x 2 chunks)
    const int l_row  = tid >> 1;         // 0..63
    const int l_half = (tid & 1) * 8;    // 0 or 8
    // B cp.async mapping (128 threads x 2 chunks): 16 k-rows x 8 chunks
    const int bk_row = tid >> 3;         // 0..15
    const int bk_chk = (tid & 7) * 8;    // 0..56 (n offset)

    // A ldmatrix lane addressing
    const int a_r = lane & 15;
    const int a_c = (lane >> 4) << 3;
    // B ldmatrix.trans lane addressing: source row = k, col = n
    const int bt_k = ((lane >> 3) & 1) * 8 + (lane & 7);  // 0..15
    const int bt_n = (lane >> 4) << 3;                     // 0 or 8

    for (int tl = blockIdx.x; tl < total; tl += gridDim.x) {
        const int n0 = (tl >> 5) * 64;
        const int m0 = (tl & 31) * 64;

        float c_[4][2][4];
        #pragma unroll
        for (int s = 0; s < 4; s++)
            #pragma unroll
            for (int u = 0; u < 2; u++)
                #pragma unroll
                for (int e = 0; e < 4; e++) c_[s][u][e] = 0.0f;

        auto load_stage = [&](int st, int kc) {
            unsigned stb = sbase + (unsigned)(st * K4_STAGE) * 2;
            unsigned dA = stb + (unsigned)(l_row * 24 + l_half) * 2;
            CP_ASYNC_16(dA,            g_Ah + (size_t)(m0 + l_row) * DIM + kc + l_half);
            CP_ASYNC_16(dA + 1536 * 2, g_Al + (size_t)(m0 + l_row) * DIM + kc + l_half);
            unsigned dB = stb + (unsigned)(3072 + bk_row * 72 + bk_chk) * 2;
            CP_ASYNC_16(dB,            g_Bh + (size_t)(kc + bk_row) * NMAXPAD + n0 + bk_chk);
            CP_ASYNC_16(dB + 1152 * 2, g_Bl + (size_t)(kc + bk_row) * NMAXPAD + n0 + bk_chk);
        };

        load_stage(0, 0);  CP_COMMIT();
        load_stage(1, 16); CP_COMMIT();
        load_stage(2, 32); CP_COMMIT();

        #pragma unroll 1
        for (int it = 0; it < 32; it++) {
            if (it < 30) { CP_WAIT2(); }
            else if (it == 30) { CP_WAIT1(); }
            else { CP_WAIT0(); }
            __syncthreads();
            if (it < 29) { load_stage((it + 3) & 3, (it + 3) * 16); CP_COMMIT(); }

            unsigned stb = sbase + (unsigned)((it & 3) * K4_STAGE) * 2;
            unsigned afh[4][4], afl[4][4], bh[4], bl[4];
            #pragma unroll
            for (int s = 0; s < 4; s++) {
                int r = s * 16 + a_r;
                unsigned aH = stb + (unsigned)(r * 24 + a_c) * 2;
                LDSM_X4(afh[s][0], afh[s][1], afh[s][2], afh[s][3], aH);
                LDSM_X4(afl[s][0], afl[s][1], afl[s][2], afl[s][3], aH + 1536 * 2);
            }
            {
                unsigned aB = stb + (unsigned)(3072 + bt_k * 72 + wn * 16 + bt_n) * 2;
                LDSM_X4_T(bh[0], bh[1], bh[2], bh[3], aB);
                LDSM_X4_T(bl[0], bl[1], bl[2], bl[3], aB + 1152 * 2);
            }
            #pragma unroll
            for (int s = 0; s < 4; s++)
                #pragma unroll
                for (int u = 0; u < 2; u++) {
                    MMA_BF16(c_[s][u], afh[s], bh[2 * u], bh[2 * u + 1]);
                    MMA_BF16(c_[s][u], afh[s], bl[2 * u], bl[2 * u + 1]);
                    MMA_BF16(c_[s][u], afl[s], bh[2 * u], bh[2 * u + 1]);
                }
        }

        // epilogue: coef-weighted reduction, then width-4 shfl + atomicAdd
        #pragma unroll
        for (int s = 0; s < 4; s++) {
            int row0 = m0 + s * 16 + g;
            int row1 = row0 + 8;
            float rs0 = 0.0f, rs1 = 0.0f;
            #pragma unroll
            for (int u = 0; u < 2; u++) {
                int n = n0 + wn * 16 + u * 8 + 2 * q;
                float cf00 = coef_fn(row0, n,     Ncols, cw, cb);
                float cf01 = coef_fn(row0, n + 1, Ncols, cw, cb);
                float cf10 = coef_fn(row1, n,     Ncols, cw, cb);
                float cf11 = coef_fn(row1, n + 1, Ncols, cw, cb);
                rs0 = fmaf(c_[s][u][0], cf00, fmaf(c_[s][u][1], cf01, rs0));
                rs1 = fmaf(c_[s][u][2], cf10, fmaf(c_[s][u][3], cf11, rs1));
            }
            rs0 += __shfl_down_sync(0xffffffffu, rs0, 2, 4);
            rs0 += __shfl_down_sync(0xffffffffu, rs0, 1, 4);
            rs1 += __shfl_down_sync(0xffffffffu, rs1, 2, 4);
            rs1 += __shfl_down_sync(0xffffffffu, rs1, 1, 4);
            if (q == 0) {
                atomicAdd(&out[row0], rs0);
                atomicAdd(&out[row1], rs1);
            }
        }
        __syncthreads();   // smem stage buffers quiesce before next tile
    }
}

// ---------------------------------------------------------------------------
extern "C" void kernel_launch(void* const* d_in, const int* in_sizes, int n_in,
                              void* d_out, int out_size)
{
    const int*   h      = (const int*)  d_in[0];
    const int*   r      = (const int*)  d_in[1];
    const int*   t      = (const int*)  d_in[2];
    const float* ent    = (const float*)d_in[3];
    const float* rel    = (const float*)d_in[4];
    const float* conv_w = (const float*)d_in[5];
    const float* conv_b = (const float*)d_in[6];
    const float* proj_w = (const float*)d_in[7];
    const float* proj_b = (const float*)d_in[8];
    float* out = (float*)d_out;

    k1_gather<<<512, 256>>>(h, r, t, ent, rel, out);
    k2_classify<<<1, 128>>>(conv_w, conv_b);
    k3_build<<<512, 256>>>(proj_w, proj_b);
    k4_gemm<<<296, 128>>>(conv_w, conv_b, out);
}

// round 17
// speedup vs baseline: 1.1081x; 1.1081x over previous
#include <cuda_runtime.h>
#include <cuda_bf16.h>

// ---------------------------------------------------------------------------
// ConvTransE scoring, algebraically reduced:
//   score[i] = e_t[i]^T (proj_w @ relu(conv(x_i)+b) + proj_b),  x_i = [h_e ; r_e]
// Linear/zero channels folded into an effective 512x512 matrix; the few
// "uncertain" channels + the p==511 edge go through exact-ReLU correction
// columns of one fused GEMM. Tensor cores via hi/lo bf16 split (3x mma.sync
// m16n8k16). B kept in natural [k][n] bf16 layout (written coalesced by k3);
// k4 loads B fragments with ldmatrix.trans. K4: 8 warps per 64x64 tile.
// ---------------------------------------------------------------------------

#define BATCH    2048
#define DIM      512
#define CH       32
#define NMAXPAD  16960          // max padded N (= 265*64), row stride of Bh/Bl

__device__ __align__(16) float g_H[BATCH * DIM];     // gathered h_e rows (fp32, coefs)
__device__ __align__(16) __nv_bfloat16 g_Ah[BATCH * DIM];   // A hi [m][k]
__device__ __align__(16) __nv_bfloat16 g_Al[BATCH * DIM];   // A lo
__device__ __align__(16) __nv_bfloat16 g_Bh[512 * NMAXPAD]; // B hi [k][n] (zero-init tails)
__device__ __align__(16) __nv_bfloat16 g_Bl[512 * NMAXPAD]; // B lo [k][n]
__device__ float        g_r0[BATCH];               // rel[r[i]][0]
__device__ float        g_bmax[BATCH];             // per-row max|h_e|
__device__ float4       g_weff[CH];                // (w0,w1,w2,b) if linear else 0
__device__ int          g_unc[CH];                 // compact list of uncertain channels
__device__ int          g_uidx[CH];                // channel -> unc index or -1
__device__ int          g_N;                       // runtime #columns = 545 + 511*U

#define MMA_BF16(C, A, B0, B1) \
    asm volatile("mma.sync.aligned.m16n8k16.row.col.f32.bf16.bf16.f32 " \
        "{%0,%1,%2,%3},{%4,%5,%6,%7},{%8,%9},{%0,%1,%2,%3};" \
        : "+f"(C[0]), "+f"(C[1]), "+f"(C[2]), "+f"(C[3]) \
        : "r"(A[0]), "r"(A[1]), "r"(A[2]), "r"(A[3]), "r"(B0), "r"(B1))

#define LDSM_X4(d0, d1, d2, d3, addr) \
    asm volatile("ldmatrix.sync.aligned.m8n8.x4.shared.b16 {%0,%1,%2,%3}, [%4];" \
        : "=r"(d0), "=r"(d1), "=r"(d2), "=r"(d3) : "r"(addr))

#define LDSM_X4_T(d0, d1, d2, d3, addr) \
    asm volatile("ldmatrix.sync.aligned.m8n8.x4.trans.shared.b16 {%0,%1,%2,%3}, [%4];" \
        : "=r"(d0), "=r"(d1), "=r"(d2), "=r"(d3) : "r"(addr))

#define CP_ASYNC_16(dst, src) \
    asm volatile("cp.async.cg.shared.global [%0], [%1], 16;" :: "r"(dst), "l"(src))
#define CP_COMMIT() asm volatile("cp.async.commit_group;")
#define CP_WAIT2()  asm volatile("cp.async.wait_group 2;")
#define CP_WAIT1()  asm volatile("cp.async.wait_group 1;")
#define CP_WAIT0()  asm volatile("cp.async.wait_group 0;")

__device__ __forceinline__ void split_bf16(float v, __nv_bfloat16& hi, __nv_bfloat16& lo) {
    hi = __float2bfloat16(v);
    lo = __float2bfloat16(v - __bfloat162float(hi));
}

// ------------- K1: gather + zero scores + per-row max + A split -------------
__global__ __launch_bounds__(256) void k1_gather(
    const int* __restrict__ h, const int* __restrict__ r, const int* __restrict__ t,
    const float* __restrict__ ent, const float* __restrict__ rel,
    float* __restrict__ out)
{
    const int tid  = threadIdx.x;
    const int warp = tid >> 5;
    const int lane = tid & 31;
    const int row  = warp >> 1;          // 0..3 (block-local batch row)
    const int half = warp & 1;
    const int i    = blockIdx.x * 4 + row;
    const int f4   = half * 64 + lane;   // float4 index (0..63 within half-row)

    const float4* hs = (const float4*)(ent + (size_t)h[i] * DIM);
    const float4* ts = (const float4*)(ent + (size_t)t[i] * DIM);
    float4 hv0 = hs[f4], hv1 = hs[f4 + 32];
    float4 tv0 = ts[f4], tv1 = ts[f4 + 32];
    ((float4*)g_H)[i * 128 + f4]      = hv0;
    ((float4*)g_H)[i * 128 + f4 + 32] = hv1;
    {
        float v[8] = {tv0.x, tv0.y, tv0.z, tv0.w, tv1.x, tv1.y, tv1.z, tv1.w};
        size_t b0 = (size_t)i * DIM + f4 * 4;
        #pragma unroll
        for (int j = 0; j < 4; j++) {
            __nv_bfloat16 hi, lo;
            split_bf16(v[j], hi, lo);
            g_Ah[b0 + j] = hi;  g_Al[b0 + j] = lo;
        }
        size_t b1 = b0 + 128;
        #pragma unroll
        for (int j = 0; j < 4; j++) {
            __nv_bfloat16 hi, lo;
            split_bf16(v[4 + j], hi, lo);
            g_Ah[b1 + j] = hi;  g_Al[b1 + j] = lo;
        }
    }
    float m = fmaxf(fmaxf(fabsf(hv0.x), fabsf(hv0.y)), fmaxf(fabsf(hv0.z), fabsf(hv0.w)));
    m = fmaxf(m, fmaxf(fmaxf(fabsf(hv1.x), fabsf(hv1.y)), fmaxf(fabsf(hv1.z), fabsf(hv1.w))));
    #pragma unroll
    for (int off = 16; off > 0; off >>= 1)
        m = fmaxf(m, __shfl_xor_sync(0xffffffffu, m, off));
    __shared__ float wm_[8];
    if (lane == 0) wm_[warp] = m;
    __syncthreads();
    if (lane == 0 && half == 0) {
        g_bmax[i] = fmaxf(wm_[2 * row], wm_[2 * row + 1]);
        g_r0[i] = rel[(size_t)r[i] * DIM];
        out[i] = 0.0f;
    }
}

// ------------- K2: reduce bmax + classify + effective weights ---------------
__global__ __launch_bounds__(128) void k2_classify(
    const float* __restrict__ cw, const float* __restrict__ cb)
{
    __shared__ float sm[4];
    int tid = threadIdx.x;
    float m = 0.0f;
    #pragma unroll
    for (int j = tid; j < BATCH; j += 128) m = fmaxf(m, g_bmax[j]);
    #pragma unroll
    for (int off = 16; off > 0; off >>= 1)
        m = fmaxf(m, __shfl_xor_sync(0xffffffffu, m, off));
    if ((tid & 31) == 0) sm[tid >> 5] = m;
    __syncthreads();
    if (tid < 32) {
        float xmax = fmaxf(fmaxf(sm[0], sm[1]), fmaxf(sm[2], sm[3]));
        int c = tid;
        float w0 = cw[c*3], w1 = cw[c*3+1], w2 = cw[c*3+2], b = cb[c];
        float bound = (fabsf(w0) + fabsf(w1) + fabsf(w2)) * xmax;
        int cls = (b >= bound) ? 1 : ((b <= -bound) ? 0 : 2);
        float lin = (cls == 1) ? 1.0f : 0.0f;
        g_weff[c] = make_float4(w0 * lin, w1 * lin, w2 * lin, b * lin);
        unsigned msk = __ballot_sync(0xffffffffu, cls == 2);
        if (cls == 2) {
            int idx = __popc(msk & ((1u << c) - 1u));
            g_unc[idx] = c;
            g_uidx[c] = idx;
        } else {
            g_uidx[c] = -1;
        }
        if (c == 0) g_N = 545 + 511 * __popc(msk);
    }
}

// ------------- K3: cp.async-streamed fold conv+proj_w -> Bh/Bl [k][n] -------
#define K3_NSTG 3
__global__ __launch_bounds__(256) void k3_build(
    const float* __restrict__ pw, const float* __restrict__ pb)
{
    __shared__ __align__(16) float stg[K3_NSTG][8 * 512];   // 48KB
    __shared__ float sred[8];
    const int tid = threadIdx.x;
    const int d = blockIdx.x;
    const float* prow = pw + (size_t)d * (CH * DIM);
    const size_t drow = (size_t)d * NMAXPAD;
    const unsigned sb0 = (unsigned)__cvta_generic_to_shared(&stg[0][0]);
    const int n0 = tid * 2;

    float T0[2] = {0,0}, T1[2] = {0,0}, T2[2] = {0,0}, T3[2] = {0,0};

    auto issue = [&](int g) {
        unsigned dstb = sb0 + (unsigned)((g % K3_NSTG) * 8 * 512 * 4);
        const float* src = prow + g * 4096;
        #pragma unroll
        for (int j = 0; j < 4; j++)
            CP_ASYNC_16(dstb + (unsigned)(tid + j * 256) * 16, src + (tid + j * 256) * 4);
        CP_COMMIT();
    };
    issue(0); issue(1); issue(2);

    #pragma unroll 1
    for (int g = 0; g < 4; g++) {
        if (g <= 1) { CP_WAIT2(); }
        else if (g == 2) { CP_WAIT1(); }
        else { CP_WAIT0(); }
        __syncthreads();
        const float* buf = &stg[g % K3_NSTG][0];
        #pragma unroll
        for (int cc = 0; cc < 8; cc++) {
            int c = g * 8 + cc;
            float2 s = *(const float2*)&buf[cc * 512 + n0];
            float4 w = g_weff[c];
            T0[0] = fmaf(w.x, s.x, T0[0]); T0[1] = fmaf(w.x, s.y, T0[1]);
            T1[0] = fmaf(w.y, s.x, T1[0]); T1[1] = fmaf(w.y, s.y, T1[1]);
            T2[0] = fmaf(w.z, s.x, T2[0]); T2[1] = fmaf(w.z, s.y, T2[1]);
            T3[0] = fmaf(w.w, s.x, T3[0]); T3[1] = fmaf(w.w, s.y, T3[1]);
            if (tid == 255) {                              // edge col (p==511)
                __nv_bfloat16 hi, lo;
                split_bf16(s.y, hi, lo);
                g_Bh[drow + 513 + c] = hi;
                g_Bl[drow + 513 + c] = lo;
            }
            int ui = g_uidx[c];
            if (ui >= 0) {                                 // uncertain: exact copy
                size_t base = drow + 545 + (size_t)ui * 511;
                __nv_bfloat16 hi, lo;
                split_bf16(s.x, hi, lo);
                g_Bh[base + n0] = hi;  g_Bl[base + n0] = lo;
                if (n0 + 1 < 511) {
                    split_bf16(s.y, hi, lo);
                    g_Bh[base + n0 + 1] = hi;  g_Bl[base + n0 + 1] = lo;
                }
            }
        }
        __syncthreads();                 // reads done before ring reuse
        if (g == 0) issue(3);
    }

    // end merge: acc[n] = T0[n+1] + T1[n] + T2[n-1] via smem exchange
    float* sT = &stg[0][0];              // reuse: 3*512 floats
    sT[n0] = T0[0];        sT[n0 + 1] = T0[1];
    sT[512 + n0] = T1[0];  sT[512 + n0 + 1] = T1[1];
    sT[1024 + n0] = T2[0]; sT[1024 + n0 + 1] = T2[1];
    __syncthreads();
    {
        int na = n0, nb = n0 + 1;
        float acc0 = 0.0f, acc1 = 0.0f;
        if (na <= 509) acc0 += sT[na + 1];
        if (na <= 510) acc0 += sT[512 + na];
        if (na >= 1)   acc0 += sT[1024 + na - 1];
        if (nb <= 509) acc1 += sT[nb + 1];
        if (nb <= 510) acc1 += sT[512 + nb];
        acc1 += sT[1024 + nb - 1];       // nb >= 1 always
        __nv_bfloat16 h0, l0, h1, l1;
        split_bf16(acc0, h0, l0);
        split_bf16(acc1, h1, l1);
        __nv_bfloat162 hp; hp.x = h0; hp.y = h1;
        __nv_bfloat162 lp; lp.x = l0; lp.y = l1;
        *(__nv_bfloat162*)&g_Bh[drow + n0] = hp;
        *(__nv_bfloat162*)&g_Bl[drow + n0] = lp;
    }
    float cp = T3[0] + ((n0 + 1 <= 510) ? T3[1] : 0.0f);
    #pragma unroll
    for (int off = 16; off > 0; off >>= 1)
        cp += __shfl_xor_sync(0xffffffffu, cp, off);
    if ((tid & 31) == 0) sred[tid >> 5] = cp;
    __syncthreads();
    if (tid == 0) {
        float s = 0.0f;
        #pragma unroll
        for (int w = 0; w < 8; w++) s += sred[w];
        __nv_bfloat16 hi, lo;
        split_bf16(s + pb[d], hi, lo);
        g_Bh[drow + 512] = hi;           // const column
        g_Bl[drow + 512] = lo;
    }
}

// -------------------- coef(row, col) for the scoring epilogue ---------------
__device__ __forceinline__ float coef_fn(int row, int n, int Ncols,
                                         const float* __restrict__ cw,
                                         const float* __restrict__ cb)
{
    if (n >= Ncols) return 0.0f;
    if (n < 512)  return g_H[(size_t)row * DIM + n];
    if (n == 512) return 1.0f;
    const float* Hr = &g_H[(size_t)row * DIM];
    if (n < 545) {
        int c = n - 513;
        float v = fmaf(cw[c * 3], Hr[510],
                  fmaf(cw[c * 3 + 1], Hr[511],
                  fmaf(cw[c * 3 + 2], g_r0[row], cb[c])));
        return fmaxf(v, 0.0f);
    }
    int q = n - 545;
    int ui = q / 511;
    int p = q - ui * 511;                // p in [0, 510]
    int c = g_unc[ui];
    float xm1 = (p == 0) ? 0.0f : Hr[p - 1];
    float v = fmaf(cw[c * 3], xm1,
              fmaf(cw[c * 3 + 1], Hr[p],
              fmaf(cw[c * 3 + 2], Hr[p + 1], cb[c])));
    return fmaxf(v, 0.0f);
}

// ---------- K4: persistent tensor-core GEMM + fused scoring (grid-stride) ---
// 64(m) x 64(n) tiles, k-tile 16, 4-stage cp.async ring (43KB static smem),
// 256 threads / 8 warps per tile: wm = warp>>2 (m 32-half), wn = warp&3
// (n 16-slice). Per warp: 2 m16-subtiles x 2 n8-subtiles, 12 MMAs/iter.
// A fragments via ldmatrix (24-elem rows); B via ldmatrix.trans (72-elem rows).
// Stage layout (bf16 elements): AH 0 (64x24), AL 1536, BH 3072 (16x72), BL 4224.
#define K4_STAGE 5376

__global__ __launch_bounds__(256) void k4_gemm(
    const float* __restrict__ cw, const float* __restrict__ cb,
    float* __restrict__ out)
{
    const int Ncols = g_N;
    const int ntn = (Ncols + 63) >> 6;
    const int total = ntn * 32;          // 32 m-tiles of 64

    __shared__ __align__(16) __nv_bfloat16 smem[4 * K4_STAGE];   // 43,008 B
    const unsigned sbase = (unsigned)__cvta_generic_to_shared(smem);

    const int tid  = threadIdx.x;
    const int lane = tid & 31;
    const int warp = tid >> 5;           // 0..7
    const int wm   = warp >> 2;          // 0..1 (m 32-half)
    const int wn   = warp & 3;           // 0..3 (n 16-slice)
    const int g = lane >> 2;             // 0..7
    const int q = lane & 3;              // 0..3

    // cp.async mapping: threads 0-127 load A(hi/lo), 128-255 load B(hi/lo)
    const int a_row  = (tid & 127) >> 1;     // 0..63
    const int a_half = (tid & 1) * 8;        // 0 or 8
    const int bk_row = (tid & 127) >> 3;     // 0..15
    const int bk_chk = (tid & 7) * 8;        // 0..56

    // A ldmatrix lane addressing
    const int a_r = lane & 15;
    const int a_c = (lane >> 4) << 3;
    // B ldmatrix.trans lane addressing: source row = k, col = n
    const int bt_k = ((lane >> 3) & 1) * 8 + (lane & 7);  // 0..15
    const int bt_n = (lane >> 4) << 3;                     // 0 or 8

    for (int tl = blockIdx.x; tl < total; tl += gridDim.x) {
        const int n0 = (tl >> 5) * 64;
        const int m0 = (tl & 31) * 64;

        float c_[2][2][4];
        #pragma unroll
        for (int s = 0; s < 2; s++)
            #pragma unroll
            for (int u = 0; u < 2; u++)
                #pragma unroll
                for (int e = 0; e < 4; e++) c_[s][u][e] = 0.0f;

        auto load_stage = [&](int st, int kc) {
            unsigned stb = sbase + (unsigned)(st * K4_STAGE) * 2;
            if (tid < 128) {
                unsigned dA = stb + (unsigned)(a_row * 24 + a_half) * 2;
                CP_ASYNC_16(dA,            g_Ah + (size_t)(m0 + a_row) * DIM + kc + a_half);
                CP_ASYNC_16(dA + 1536 * 2, g_Al + (size_t)(m0 + a_row) * DIM + kc + a_half);
            } else {
                unsigned dB = stb + (unsigned)(3072 + bk_row * 72 + bk_chk) * 2;
                CP_ASYNC_16(dB,            g_Bh + (size_t)(kc + bk_row) * NMAXPAD + n0 + bk_chk);
                CP_ASYNC_16(dB + 1152 * 2, g_Bl + (size_t)(kc + bk_row) * NMAXPAD + n0 + bk_chk);
            }
        };

        load_stage(0, 0);  CP_COMMIT();
        load_stage(1, 16); CP_COMMIT();
        load_stage(2, 32); CP_COMMIT();

        #pragma unroll 1
        for (int it = 0; it < 32; it++) {
            if (it < 30) { CP_WAIT2(); }
            else if (it == 30) { CP_WAIT1(); }
            else { CP_WAIT0(); }
            __syncthreads();
            if (it < 29) { load_stage((it + 3) & 3, (it + 3) * 16); CP_COMMIT(); }

            unsigned stb = sbase + (unsigned)((it & 3) * K4_STAGE) * 2;
            unsigned afh[2][4], afl[2][4], bh[4], bl[4];
            #pragma unroll
            for (int s = 0; s < 2; s++) {
                int r = wm * 32 + s * 16 + a_r;
                unsigned aH = stb + (unsigned)(r * 24 + a_c) * 2;
                LDSM_X4(afh[s][0], afh[s][1], afh[s][2], afh[s][3], aH);
                LDSM_X4(afl[s][0], afl[s][1], afl[s][2], afl[s][3], aH + 1536 * 2);
            }
            {
                unsigned aB = stb + (unsigned)(3072 + bt_k * 72 + wn * 16 + bt_n) * 2;
                LDSM_X4_T(bh[0], bh[1], bh[2], bh[3], aB);
                LDSM_X4_T(bl[0], bl[1], bl[2], bl[3], aB + 1152 * 2);
            }
            #pragma unroll
            for (int s = 0; s < 2; s++)
                #pragma unroll
                for (int u = 0; u < 2; u++) {
                    MMA_BF16(c_[s][u], afh[s], bh[2 * u], bh[2 * u + 1]);
                    MMA_BF16(c_[s][u], afh[s], bl[2 * u], bl[2 * u + 1]);
                    MMA_BF16(c_[s][u], afl[s], bh[2 * u], bh[2 * u + 1]);
                }
        }

        // epilogue: coef-weighted reduction, then width-4 shfl + atomicAdd
        #pragma unroll
        for (int s = 0; s < 2; s++) {
            int row0 = m0 + wm * 32 + s * 16 + g;
            int row1 = row0 + 8;
            float rs0 = 0.0f, rs1 = 0.0f;
            #pragma unroll
            for (int u = 0; u < 2; u++) {
                int n = n0 + wn * 16 + u * 8 + 2 * q;
                float cf00 = coef_fn(row0, n,     Ncols, cw, cb);
                float cf01 = coef_fn(row0, n + 1, Ncols, cw, cb);
                float cf10 = coef_fn(row1, n,     Ncols, cw, cb);
                float cf11 = coef_fn(row1, n + 1, Ncols, cw, cb);
                rs0 = fmaf(c_[s][u][0], cf00, fmaf(c_[s][u][1], cf01, rs0));
                rs1 = fmaf(c_[s][u][2], cf10, fmaf(c_[s][u][3], cf11, rs1));
            }
            rs0 += __shfl_down_sync(0xffffffffu, rs0, 2, 4);
            rs0 += __shfl_down_sync(0xffffffffu, rs0, 1, 4);
            rs1 += __shfl_down_sync(0xffffffffu, rs1, 2, 4);
            rs1 += __shfl_down_sync(0xffffffffu, rs1, 1, 4);
            if (q == 0) {
                atomicAdd(&out[row0], rs0);
                atomicAdd(&out[row1], rs1);
            }
        }
        __syncthreads();   // smem stage buffers quiesce before next tile
    }
}

// ---------------------------------------------------------------------------
extern "C" void kernel_launch(void* const* d_in, const int* in_sizes, int n_in,
                              void* d_out, int out_size)
{
    const int*   h      = (const int*)  d_in[0];
    const int*   r      = (const int*)  d_in[1];
    const int*   t      = (const int*)  d_in[2];
    const float* ent    = (const float*)d_in[3];
    const float* rel    = (const float*)d_in[4];
    const float* conv_w = (const float*)d_in[5];
    const float* conv_b = (const float*)d_in[6];
    const float* proj_w = (const float*)d_in[7];
    const float* proj_b = (const float*)d_in[8];
    float* out = (float*)d_out;

    k1_gather<<<512, 256>>>(h, r, t, ent, rel, out);
    k2_classify<<<1, 128>>>(conv_w, conv_b);
    k3_build<<<512, 256>>>(proj_w, proj_b);
    k4_gemm<<<296, 256>>>(conv_w, conv_b, out);
}